// round 1
// baseline (speedup 1.0000x reference)
#include <cuda_runtime.h>
#include <math.h>

#define B_   4
#define S_   2048
#define DM   1024
#define NH   16
#define HD   64

// Scratch: Q/K/V in [B, H, S, Dh] layout (32 MB each).
__device__ float g_Q[B_ * NH * S_ * HD];
__device__ float g_K[B_ * NH * S_ * HD];
__device__ float g_V[B_ * NH * S_ * HD];

// ---------------------------------------------------------------------------
// Kernel A: fused QKV projection + degenerate-RoPE scale + transpose-store.
// out[n, o] = sum_k x[n,k] * W[o,k]   (nn.Linear: x @ W.T)
// Grid: (M/64, 3072/64). Block 256 threads, 64x64 tile, 4x4 per thread.
// ---------------------------------------------------------------------------
__global__ __launch_bounds__(256) void qkv_kernel(
    const float* __restrict__ x,
    const float* __restrict__ Wq,
    const float* __restrict__ Wk,
    const float* __restrict__ Wv)
{
    __shared__ float a_s[16][68];   // x tile, transposed [k][m]
    __shared__ float b_s[16][68];   // W tile, transposed [k][o]

    const int bm  = blockIdx.x;            // 0..127
    const int bn  = blockIdx.y;            // 0..47
    const int tid = threadIdx.x;
    const int tx  = tid & 15;              // N direction
    const int ty  = tid >> 4;              // M direction

    const int which = bn >> 4;             // 0=Q, 1=K, 2=V
    const float* W  = (which == 0) ? Wq : ((which == 1) ? Wk : Wv);
    const int ocol0 = (bn & 15) * 64;      // column offset within this W's 1024
    const int row0  = bm * 64;             // global row (n = b*S + s)

    const int lm = tid >> 2;               // 0..63: row of the 64x16 tile
    const int lk = (tid & 3) * 4;          // 0,4,8,12

    float acc[4][4] = {};

    for (int k0 = 0; k0 < DM; k0 += 16) {
        float4 xa = *(const float4*)&x[(size_t)(row0 + lm) * DM + k0 + lk];
        float4 wb = *(const float4*)&W[(size_t)(ocol0 + lm) * DM + k0 + lk];
        __syncthreads();
        a_s[lk + 0][lm] = xa.x; a_s[lk + 1][lm] = xa.y;
        a_s[lk + 2][lm] = xa.z; a_s[lk + 3][lm] = xa.w;
        b_s[lk + 0][lm] = wb.x; b_s[lk + 1][lm] = wb.y;
        b_s[lk + 2][lm] = wb.z; b_s[lk + 3][lm] = wb.w;
        __syncthreads();

        #pragma unroll
        for (int k = 0; k < 16; k++) {
            float4 av = *(const float4*)&a_s[k][ty * 4];
            float4 bv = *(const float4*)&b_s[k][tx * 4];
            float a0 = av.x, a1 = av.y, a2 = av.z, a3 = av.w;
            float b0 = bv.x, b1 = bv.y, b2 = bv.z, b3 = bv.w;
            acc[0][0] += a0 * b0; acc[0][1] += a0 * b1; acc[0][2] += a0 * b2; acc[0][3] += a0 * b3;
            acc[1][0] += a1 * b0; acc[1][1] += a1 * b1; acc[1][2] += a1 * b2; acc[1][3] += a1 * b3;
            acc[2][0] += a2 * b0; acc[2][1] += a2 * b1; acc[2][2] += a2 * b2; acc[2][3] += a2 * b3;
            acc[3][0] += a3 * b0; acc[3][1] += a3 * b1; acc[3][2] += a3 * b2; acc[3][3] += a3 * b3;
        }
    }

    // Degenerate RoPE: y_d = x_d * (cos a + sin a) for d<32, x_d * (cos a - sin a)
    // for d>=32, with a = batch_idx * 10000^(-j/32), j = d mod 32.
    // Block never straddles a batch boundary (64 | 2048).
    const int b_idx = row0 >> 11;  // row0 / 2048
    float f[4];
    #pragma unroll
    for (int j = 0; j < 4; j++) {
        const int col = ocol0 + tx * 4 + j;
        const int d   = col & 63;
        if (which < 2) {
            const int jj = d & 31;
            float th = expf(-(float)jj * (logf(10000.0f) / 32.0f));
            float sa, ca;
            sincosf((float)b_idx * th, &sa, &ca);
            f[j] = (d < 32) ? (ca + sa) : (ca - sa);
        } else {
            f[j] = 1.0f;
        }
    }

    float* dst = (which == 0) ? g_Q : ((which == 1) ? g_K : g_V);
    #pragma unroll
    for (int i = 0; i < 4; i++) {
        const int row = row0 + ty * 4 + i;
        const int s   = row & (S_ - 1);
        const int b   = row >> 11;
        #pragma unroll
        for (int j = 0; j < 4; j++) {
            const int col = ocol0 + tx * 4 + j;
            const int h   = col >> 6;
            const int d   = col & 63;
            dst[((size_t)(b * NH + h) * S_ + s) * HD + d] = acc[i][j] * f[j];
        }
    }
}

// ---------------------------------------------------------------------------
// Kernel B: flash attention, fp32. One block = 64 query rows of one (b,h).
// 256 threads: thread t owns query row r = t/4, column quarter part = t%4
// (16 score columns / 16 output dims).
// ---------------------------------------------------------------------------
__global__ __launch_bounds__(256) void attn_kernel(float* __restrict__ out)
{
    extern __shared__ float sm[];
    float* q_s = sm;                 // [64][65]
    float* k_s = q_s + 64 * 65;      // [d][c]  64*64
    float* v_s = k_s + 64 * 64;      // [c][d]  64*64
    float* p_s = v_s + 64 * 64;      // [64][65]

    const int qt  = blockIdx.x;      // 0..31
    const int h   = blockIdx.y;      // 0..15
    const int b   = blockIdx.z;      // 0..3
    const int tid = threadIdx.x;
    const int r    = tid >> 2;       // query row within tile
    const int part = tid & 3;        // column quarter

    const size_t bh_off = (size_t)(b * NH + h) * S_ * HD;
    const float* Q = g_Q + bh_off;
    const float* K = g_K + bh_off;
    const float* V = g_V + bh_off;
    const int q0 = qt * 64;

    // Load Q tile once: q_s[r][d], pitch 65.
    {
        const int lr = tid >> 2;
        const int ld = (tid & 3) * 16;
        #pragma unroll
        for (int j = 0; j < 4; j++) {
            float4 qv = *(const float4*)&Q[(size_t)(q0 + lr) * HD + ld + 4 * j];
            q_s[lr * 65 + ld + 4 * j + 0] = qv.x;
            q_s[lr * 65 + ld + 4 * j + 1] = qv.y;
            q_s[lr * 65 + ld + 4 * j + 2] = qv.z;
            q_s[lr * 65 + ld + 4 * j + 3] = qv.w;
        }
    }

    float m = -INFINITY, l = 0.0f;
    float o[16];
    #pragma unroll
    for (int i = 0; i < 16; i++) o[i] = 0.0f;

    for (int kk0 = 0; kk0 < S_; kk0 += 64) {
        __syncthreads();
        // Load K tile transposed (k_s[d][c]) and V tile direct (v_s[c][d]).
        {
            const int c    = tid >> 2;
            const int dblk = (tid & 3) * 16;
            #pragma unroll
            for (int j = 0; j < 4; j++) {
                float4 kv = *(const float4*)&K[(size_t)(kk0 + c) * HD + dblk + 4 * j];
                k_s[(dblk + 4 * j + 0) * 64 + c] = kv.x;
                k_s[(dblk + 4 * j + 1) * 64 + c] = kv.y;
                k_s[(dblk + 4 * j + 2) * 64 + c] = kv.z;
                k_s[(dblk + 4 * j + 3) * 64 + c] = kv.w;
                float4 vv = *(const float4*)&V[(size_t)(kk0 + c) * HD + dblk + 4 * j];
                *(float4*)&v_s[c * 64 + dblk + 4 * j] = vv;
            }
        }
        __syncthreads();

        // Scores: s[i] = sum_d q[r][d] * k[kk0 + part*16 + i][d]
        float s[16];
        #pragma unroll
        for (int i = 0; i < 16; i++) s[i] = 0.0f;
        #pragma unroll 8
        for (int d = 0; d < 64; d++) {
            float qv = q_s[r * 65 + d];
            const float4* kp = (const float4*)&k_s[d * 64 + part * 16];
            float4 k0 = kp[0], k1 = kp[1], k2 = kp[2], k3 = kp[3];
            s[0]  += qv * k0.x; s[1]  += qv * k0.y; s[2]  += qv * k0.z; s[3]  += qv * k0.w;
            s[4]  += qv * k1.x; s[5]  += qv * k1.y; s[6]  += qv * k1.z; s[7]  += qv * k1.w;
            s[8]  += qv * k2.x; s[9]  += qv * k2.y; s[10] += qv * k2.z; s[11] += qv * k2.w;
            s[12] += qv * k3.x; s[13] += qv * k3.y; s[14] += qv * k3.z; s[15] += qv * k3.w;
        }

        // Online softmax (4 threads per row; consecutive lanes -> shfl_xor 1,2).
        float mt = -INFINITY;
        #pragma unroll
        for (int i = 0; i < 16; i++) {
            s[i] *= 0.125f;   // 1/sqrt(64)
            mt = fmaxf(mt, s[i]);
        }
        mt = fmaxf(mt, __shfl_xor_sync(0xffffffffu, mt, 1));
        mt = fmaxf(mt, __shfl_xor_sync(0xffffffffu, mt, 2));
        const float mnew = fmaxf(m, mt);
        const float corr = __expf(m - mnew);
        float rl = 0.0f;
        #pragma unroll
        for (int i = 0; i < 16; i++) {
            s[i] = __expf(s[i] - mnew);
            rl += s[i];
        }
        rl += __shfl_xor_sync(0xffffffffu, rl, 1);
        rl += __shfl_xor_sync(0xffffffffu, rl, 2);
        l = l * corr + rl;
        m = mnew;
        #pragma unroll
        for (int i = 0; i < 16; i++) o[i] *= corr;

        // Publish P tile for the PV GEMM.
        #pragma unroll
        for (int i = 0; i < 16; i++) p_s[r * 65 + part * 16 + i] = s[i];
        __syncthreads();

        // o[j] += sum_c p[r][c] * v[c][part*16 + j]
        #pragma unroll 8
        for (int c = 0; c < 64; c++) {
            float pv = p_s[r * 65 + c];
            const float4* vp = (const float4*)&v_s[c * 64 + part * 16];
            float4 v0 = vp[0], v1 = vp[1], v2 = vp[2], v3 = vp[3];
            o[0]  += pv * v0.x; o[1]  += pv * v0.y; o[2]  += pv * v0.z; o[3]  += pv * v0.w;
            o[4]  += pv * v1.x; o[5]  += pv * v1.y; o[6]  += pv * v1.z; o[7]  += pv * v1.w;
            o[8]  += pv * v2.x; o[9]  += pv * v2.y; o[10] += pv * v2.z; o[11] += pv * v2.w;
            o[12] += pv * v3.x; o[13] += pv * v3.y; o[14] += pv * v3.z; o[15] += pv * v3.w;
        }
    }

    // Final normalize + store to [B, S, D] with D index = h*64 + dh.
    const float inv = 1.0f / l;
    float* orow = out + ((size_t)(b * S_ + q0 + r)) * DM + h * HD + part * 16;
    #pragma unroll
    for (int j = 0; j < 4; j++) {
        float4 ov;
        ov.x = o[4 * j + 0] * inv;
        ov.y = o[4 * j + 1] * inv;
        ov.z = o[4 * j + 2] * inv;
        ov.w = o[4 * j + 3] * inv;
        *(float4*)&orow[4 * j] = ov;
    }
}

// ---------------------------------------------------------------------------
extern "C" void kernel_launch(void* const* d_in, const int* in_sizes, int n_in,
                              void* d_out, int out_size)
{
    const float* x  = (const float*)d_in[0];
    const float* Wq = (const float*)d_in[1];
    const float* Wk = (const float*)d_in[2];
    const float* Wv = (const float*)d_in[3];
    float* out = (float*)d_out;

    dim3 gA(128, 48);
    qkv_kernel<<<gA, 256>>>(x, Wq, Wk, Wv);

    const size_t smem = (size_t)(64 * 65 * 2 + 64 * 64 * 2) * sizeof(float);
    cudaFuncSetAttribute(attn_kernel, cudaFuncAttributeMaxDynamicSharedMemorySize, (int)smem);
    dim3 gB(32, 16, 4);
    attn_kernel<<<gB, 256, smem>>>(out);
}